// round 1
// baseline (speedup 1.0000x reference)
#include <cuda_runtime.h>
#include <cuda_bf16.h>
#include <math_constants.h>

#define FIVE_K 6
#define OUT_N  512
#define IN_N   1024
#define HID_N  32
#define B_N    256

// scratch (allocation-free: __device__ globals)
__device__ float g_inT[IN_N * B_N];      // inputs transposed: [IN][B], 1 MB
__device__ int   g_idx[OUT_N * FIVE_K];  // top-6 indices per output unit

// ---------------------------------------------------------------------------
// Kernel 1: top-6 per row of mask (512 rows x 1024). One warp per row.
// Each lane holds 32 values in registers; 6 iterations of warp argmax with
// tie-break toward smaller global index (matches jax top_k for distinct vals).
// ---------------------------------------------------------------------------
__global__ void topk6_kernel(const float* __restrict__ mask)
{
    int warp = (blockIdx.x * blockDim.x + threadIdx.x) >> 5;
    int lane = threadIdx.x & 31;
    if (warp >= OUT_N) return;

    const float* row = mask + warp * IN_N;
    float v[32];
#pragma unroll
    for (int c = 0; c < 32; c++)
        v[c] = row[c * 32 + lane];          // global index = c*32 + lane

#pragma unroll
    for (int it = 0; it < FIVE_K; it++) {
        // local argmax (ascending c + strict '>' -> smallest index on tie)
        float best = -CUDART_INF_F;
        int   bc   = 0;
#pragma unroll
        for (int c = 0; c < 32; c++)
            if (v[c] > best) { best = v[c]; bc = c; }
        int gi = bc * 32 + lane;

        // butterfly reduce (value desc, index asc on ties) -> all lanes agree
#pragma unroll
        for (int off = 16; off >= 1; off >>= 1) {
            float ob = __shfl_xor_sync(0xFFFFFFFFu, best, off);
            int   og = __shfl_xor_sync(0xFFFFFFFFu, gi,   off);
            if (ob > best || (ob == best && og < gi)) { best = ob; gi = og; }
        }
        if (lane == 0) g_idx[warp * FIVE_K + it] = gi;

        // knock out the winner (keep v[] in registers: unrolled static index)
        if ((gi & 31) == lane) {
            int kc = gi >> 5;
#pragma unroll
            for (int c = 0; c < 32; c++)
                if (c == kc) v[c] = -CUDART_INF_F;
        }
    }
}

// ---------------------------------------------------------------------------
// Kernel 2: transpose inputs [B][IN] -> g_inT [IN][B] so per-unit column
// gathers in the MLP kernel are coalesced.
// ---------------------------------------------------------------------------
__global__ void transpose_kernel(const float* __restrict__ inputs)
{
    int t = blockIdx.x * blockDim.x + threadIdx.x;  // coalesced read
    if (t >= IN_N * B_N) return;
    int b = t / IN_N;
    int i = t - b * IN_N;
    g_inT[i * B_N + b] = inputs[t];
}

// ---------------------------------------------------------------------------
// Kernel 3: one block per output unit o; 256 threads = batch elements.
// Weights for unit o staged in smem (broadcast reads), activations in regs.
// ---------------------------------------------------------------------------
__global__ __launch_bounds__(B_N, 2)
void mlp_kernel(const float* __restrict__ W1,
                const float* __restrict__ W2,
                const float* __restrict__ W3,
                const float* __restrict__ W4,
                float* __restrict__ out)
{
    __shared__ float sX[FIVE_K * B_N];     // gathered input columns, 6 KB
    __shared__ float sW1[FIVE_K * HID_N];  // 768 B
    __shared__ float sW2[HID_N * HID_N];   // 4 KB
    __shared__ float sW3[HID_N * HID_N];   // 4 KB
    __shared__ float sW4[HID_N];
    __shared__ int   sIdx[FIVE_K];

    const int o   = blockIdx.x;
    const int tid = threadIdx.x;

    if (tid < FIVE_K) sIdx[tid] = g_idx[o * FIVE_K + tid];
    __syncthreads();

    // gather the 6 needed input columns (coalesced from g_inT)
#pragma unroll
    for (int j = 0; j < FIVE_K; j++)
        sX[j * B_N + tid] = g_inT[sIdx[j] * B_N + tid];

    // W1 rows for the 6 selected features: 6*32 = 192 floats
    if (tid < FIVE_K * HID_N) {
        int j = tid >> 5, h = tid & 31;
        sW1[tid] = W1[(o * IN_N + sIdx[j]) * HID_N + h];
    }
    // W2 / W3: 1024 floats each = 256 float4, one per thread
    reinterpret_cast<float4*>(sW2)[tid] =
        reinterpret_cast<const float4*>(W2 + o * HID_N * HID_N)[tid];
    reinterpret_cast<float4*>(sW3)[tid] =
        reinterpret_cast<const float4*>(W3 + o * HID_N * HID_N)[tid];
    if (tid < HID_N) sW4[tid] = W4[o * HID_N + tid];
    __syncthreads();

    // ---- layer 1: 6 -> 32 ----
    float x[FIVE_K];
#pragma unroll
    for (int j = 0; j < FIVE_K; j++) x[j] = sX[j * B_N + tid];

    float h1[HID_N];
#pragma unroll
    for (int kk = 0; kk < 8; kk++) {
        float4 acc = make_float4(0.f, 0.f, 0.f, 0.f);
#pragma unroll
        for (int j = 0; j < FIVE_K; j++) {
            float4 w = *reinterpret_cast<const float4*>(sW1 + j * HID_N + kk * 4);
            float a = x[j];
            acc.x = fmaf(a, w.x, acc.x); acc.y = fmaf(a, w.y, acc.y);
            acc.z = fmaf(a, w.z, acc.z); acc.w = fmaf(a, w.w, acc.w);
        }
        h1[kk * 4 + 0] = fmaxf(acc.x, 0.f);
        h1[kk * 4 + 1] = fmaxf(acc.y, 0.f);
        h1[kk * 4 + 2] = fmaxf(acc.z, 0.f);
        h1[kk * 4 + 3] = fmaxf(acc.w, 0.f);
    }

    // ---- layer 2: 32 -> 32 ----
    float h2[HID_N];
#pragma unroll
    for (int kk = 0; kk < 8; kk++) {
        float4 acc = make_float4(0.f, 0.f, 0.f, 0.f);
#pragma unroll
        for (int h = 0; h < HID_N; h++) {
            float4 w = *reinterpret_cast<const float4*>(sW2 + h * HID_N + kk * 4);
            float a = h1[h];
            acc.x = fmaf(a, w.x, acc.x); acc.y = fmaf(a, w.y, acc.y);
            acc.z = fmaf(a, w.z, acc.z); acc.w = fmaf(a, w.w, acc.w);
        }
        h2[kk * 4 + 0] = fmaxf(acc.x, 0.f);
        h2[kk * 4 + 1] = fmaxf(acc.y, 0.f);
        h2[kk * 4 + 2] = fmaxf(acc.z, 0.f);
        h2[kk * 4 + 3] = fmaxf(acc.w, 0.f);
    }

    // ---- layer 3: 32 -> 32 (reuse h1 as output storage) ----
#pragma unroll
    for (int kk = 0; kk < 8; kk++) {
        float4 acc = make_float4(0.f, 0.f, 0.f, 0.f);
#pragma unroll
        for (int h = 0; h < HID_N; h++) {
            float4 w = *reinterpret_cast<const float4*>(sW3 + h * HID_N + kk * 4);
            float a = h2[h];
            acc.x = fmaf(a, w.x, acc.x); acc.y = fmaf(a, w.y, acc.y);
            acc.z = fmaf(a, w.z, acc.z); acc.w = fmaf(a, w.w, acc.w);
        }
        h1[kk * 4 + 0] = fmaxf(acc.x, 0.f);
        h1[kk * 4 + 1] = fmaxf(acc.y, 0.f);
        h1[kk * 4 + 2] = fmaxf(acc.z, 0.f);
        h1[kk * 4 + 3] = fmaxf(acc.w, 0.f);
    }

    // ---- layer 4: 32 -> 1, then sign (sigmoid(z)>=0.5 <=> z>=0) ----
    float acc = 0.f;
#pragma unroll
    for (int h = 0; h < HID_N; h++)
        acc = fmaf(h1[h], sW4[h], acc);

    out[tid * OUT_N + o] = (acc >= 0.f) ? 1.f : -1.f;
}

// ---------------------------------------------------------------------------
extern "C" void kernel_launch(void* const* d_in, const int* in_sizes, int n_in,
                              void* d_out, int out_size)
{
    const float* inputs = (const float*)d_in[0];  // (B, IN)
    const float* mask   = (const float*)d_in[1];  // (OUT, IN)
    const float* W1     = (const float*)d_in[2];  // (OUT, IN, HID)
    const float* W2     = (const float*)d_in[3];  // (OUT, HID, HID)
    const float* W3     = (const float*)d_in[4];  // (OUT, HID, HID)
    const float* W4     = (const float*)d_in[5];  // (OUT, HID, 1)
    float* out = (float*)d_out;                   // (B, OUT)

    // 512 warps -> 64 blocks of 8 warps
    topk6_kernel<<<(OUT_N * 32 + 255) / 256, 256>>>(mask);
    transpose_kernel<<<(IN_N * B_N + 255) / 256, 256>>>(inputs);
    mlp_kernel<<<OUT_N, B_N>>>(W1, W2, W3, W4, out);
}

// round 2
// speedup vs baseline: 1.2002x; 1.2002x over previous
#include <cuda_runtime.h>
#include <cuda_bf16.h>

#define FIVE_K 6
#define OUT_N  512
#define IN_N   1024
#define HID_N  32
#define B_N    256

typedef unsigned long long ull;

// scratch (allocation-free: __device__ globals)
__device__ float g_inT[IN_N * B_N];      // inputs transposed: [IN][B], 1 MB
__device__ int   g_idx[OUT_N * FIVE_K];  // top-6 indices per output unit

// ---------------------------------------------------------------------------
// f32x2 packed helpers (FFMA2 — ptxas never emits these from C++)
// ---------------------------------------------------------------------------
__device__ __forceinline__ ull pack2(float a, float b) {
    ull r;
    asm("mov.b64 %0, {%1, %2};"
        : "=l"(r) : "r"(__float_as_uint(a)), "r"(__float_as_uint(b)));
    return r;
}
__device__ __forceinline__ ull pdup(float a) {
    ull r;
    asm("mov.b64 %0, {%1, %1};" : "=l"(r) : "r"(__float_as_uint(a)));
    return r;
}
__device__ __forceinline__ void fma2(ull& d, ull a, ull b) {
    asm("fma.rn.f32x2 %0, %1, %2, %0;" : "+l"(d) : "l"(a), "l"(b));
}
__device__ __forceinline__ void unpack2(ull v, float& lo, float& hi) {
    unsigned ulo, uhi;
    asm("mov.b64 {%0, %1}, %2;" : "=r"(ulo), "=r"(uhi) : "l"(v));
    lo = __uint_as_float(ulo);
    hi = __uint_as_float(uhi);
}

// ---------------------------------------------------------------------------
// Kernel 1: top-6 per row of mask. One 32-thread block per row (512 blocks).
// 64-bit keys: (orderable_value << 10) | (1023 - idx)  -> max key == argmax
// with ties broken toward the smaller index. Tree + butterfly, all parallel.
// ---------------------------------------------------------------------------
__device__ __forceinline__ ull mk_key(float x, int gi) {
    unsigned u = __float_as_uint(x);
    unsigned ord = (u & 0x80000000u) ? ~u : (u | 0x80000000u);
    return ((ull)ord << 10) | (ull)(1023 - gi);
}

__global__ void topk6_kernel(const float* __restrict__ mask)
{
    const int row  = blockIdx.x;
    const int lane = threadIdx.x;

    const float4* rf4 = reinterpret_cast<const float4*>(mask + row * IN_N);
    ull k[32];
#pragma unroll
    for (int c = 0; c < 8; c++) {
        float4 v = rf4[c * 32 + lane];
        int gb = 4 * (c * 32 + lane);
        k[c * 4 + 0] = mk_key(v.x, gb + 0);
        k[c * 4 + 1] = mk_key(v.y, gb + 1);
        k[c * 4 + 2] = mk_key(v.z, gb + 2);
        k[c * 4 + 3] = mk_key(v.w, gb + 3);
    }

#pragma unroll
    for (int it = 0; it < FIVE_K; it++) {
        // 5-level register tree max (fully parallel)
        ull t[16];
#pragma unroll
        for (int i = 0; i < 16; i++) t[i] = (k[i] > k[i + 16]) ? k[i] : k[i + 16];
#pragma unroll
        for (int i = 0; i < 8; i++)  t[i] = (t[i] > t[i + 8]) ? t[i] : t[i + 8];
#pragma unroll
        for (int i = 0; i < 4; i++)  t[i] = (t[i] > t[i + 4]) ? t[i] : t[i + 4];
        t[0] = (t[0] > t[2]) ? t[0] : t[2];
        t[1] = (t[1] > t[3]) ? t[1] : t[3];
        ull best = (t[0] > t[1]) ? t[0] : t[1];

        // warp butterfly (64-bit shfl)
#pragma unroll
        for (int off = 16; off >= 1; off >>= 1) {
            ull o = __shfl_xor_sync(0xFFFFFFFFu, best, off);
            if (o > best) best = o;
        }
        if (lane == 0)
            g_idx[row * FIVE_K + it] = 1023 - (int)(best & 1023ull);

        // knockout (keys are unique: exact compare)
#pragma unroll
        for (int c = 0; c < 32; c++)
            if (k[c] == best) k[c] = 0ull;
    }
}

// ---------------------------------------------------------------------------
// Kernel 2: tiled transpose inputs [B][IN] -> g_inT [IN][B] (coalesced both
// sides).  grid (IN/32, B/32), block (32, 8).
// ---------------------------------------------------------------------------
__global__ void transpose_kernel(const float* __restrict__ inputs)
{
    __shared__ float tile[32][33];
    const int xi = blockIdx.x * 32 + threadIdx.x;   // IN index (read)
    const int yb = blockIdx.y * 32;                 // B tile base
#pragma unroll
    for (int j = 0; j < 32; j += 8)
        tile[threadIdx.y + j][threadIdx.x] = inputs[(yb + threadIdx.y + j) * IN_N + xi];
    __syncthreads();
    const int xo = blockIdx.x * 32;                 // IN tile base (write rows)
#pragma unroll
    for (int j = 0; j < 32; j += 8)
        g_inT[(xo + threadIdx.y + j) * B_N + yb + threadIdx.x] =
            tile[threadIdx.x][threadIdx.y + j];
}

// ---------------------------------------------------------------------------
// Kernel 3: 2 blocks (of 128 threads) per output unit o; each thread = one
// batch element. All FMA work in packed f32x2 (output pairs), weights staged
// in smem and loaded as natural LDS.128 (two packed pairs per load).
// ---------------------------------------------------------------------------
__global__ __launch_bounds__(128)
void mlp_kernel(const float* __restrict__ W1,
                const float* __restrict__ W2,
                const float* __restrict__ W3,
                const float* __restrict__ W4,
                float* __restrict__ out)
{
    __shared__ float sW1[FIVE_K * HID_N];   // 768 B
    __shared__ float sW2[HID_N * HID_N];    // 4 KB
    __shared__ float sW3[HID_N * HID_N];    // 4 KB
    __shared__ float sW4[HID_N];
    __shared__ int   sIdx[FIVE_K];

    const int o   = blockIdx.x >> 1;
    const int tid = threadIdx.x;
    const int b   = ((blockIdx.x & 1) << 7) + tid;

    if (tid < FIVE_K) sIdx[tid] = g_idx[o * FIVE_K + tid];

    // dense weights (no dependence on sIdx)
    {
        const float4* w2g = reinterpret_cast<const float4*>(W2 + o * HID_N * HID_N);
        const float4* w3g = reinterpret_cast<const float4*>(W3 + o * HID_N * HID_N);
        reinterpret_cast<float4*>(sW2)[tid]       = w2g[tid];
        reinterpret_cast<float4*>(sW2)[tid + 128] = w2g[tid + 128];
        reinterpret_cast<float4*>(sW3)[tid]       = w3g[tid];
        reinterpret_cast<float4*>(sW3)[tid + 128] = w3g[tid + 128];
        if (tid < HID_N) sW4[tid] = W4[o * HID_N + tid];
    }
    __syncthreads();   // sIdx visible

    // W1 rows for the 6 selected features
    for (int t = tid; t < FIVE_K * HID_N; t += 128) {
        int j = t >> 5, h = t & 31;
        sW1[t] = W1[(o * IN_N + sIdx[j]) * HID_N + h];
    }
    // gather the 6 input values for this batch element (coalesced)
    float x[FIVE_K];
#pragma unroll
    for (int j = 0; j < FIVE_K; j++)
        x[j] = g_inT[sIdx[j] * B_N + b];
    __syncthreads();   // sW1 ready

    ull  acc[16];
    float h[HID_N];

    // ---- layer 1: 6 -> 32 ----
#pragma unroll
    for (int q = 0; q < 16; q++) acc[q] = 0ull;
#pragma unroll
    for (int j = 0; j < FIVE_K; j++) {
        ull a2 = pdup(x[j]);
        const ulonglong2* wr = reinterpret_cast<const ulonglong2*>(sW1 + j * HID_N);
#pragma unroll
        for (int q = 0; q < 8; q++) {
            ulonglong2 w = wr[q];
            fma2(acc[2 * q],     a2, w.x);
            fma2(acc[2 * q + 1], a2, w.y);
        }
    }
#pragma unroll
    for (int q = 0; q < 16; q++) {
        float lo, hi; unpack2(acc[q], lo, hi);
        h[2 * q]     = fmaxf(lo, 0.f);
        h[2 * q + 1] = fmaxf(hi, 0.f);
    }

    // ---- layer 2: 32 -> 32 ----
#pragma unroll
    for (int q = 0; q < 16; q++) acc[q] = 0ull;
#pragma unroll
    for (int hh = 0; hh < HID_N; hh++) {
        ull a2 = pdup(h[hh]);
        const ulonglong2* wr = reinterpret_cast<const ulonglong2*>(sW2 + hh * HID_N);
#pragma unroll
        for (int q = 0; q < 8; q++) {
            ulonglong2 w = wr[q];
            fma2(acc[2 * q],     a2, w.x);
            fma2(acc[2 * q + 1], a2, w.y);
        }
    }
#pragma unroll
    for (int q = 0; q < 16; q++) {
        float lo, hi; unpack2(acc[q], lo, hi);
        h[2 * q]     = fmaxf(lo, 0.f);
        h[2 * q + 1] = fmaxf(hi, 0.f);
    }

    // ---- layer 3: 32 -> 32 ----
#pragma unroll
    for (int q = 0; q < 16; q++) acc[q] = 0ull;
#pragma unroll
    for (int hh = 0; hh < HID_N; hh++) {
        ull a2 = pdup(h[hh]);
        const ulonglong2* wr = reinterpret_cast<const ulonglong2*>(sW3 + hh * HID_N);
#pragma unroll
        for (int q = 0; q < 8; q++) {
            ulonglong2 w = wr[q];
            fma2(acc[2 * q],     a2, w.x);
            fma2(acc[2 * q + 1], a2, w.y);
        }
    }
#pragma unroll
    for (int q = 0; q < 16; q++) {
        float lo, hi; unpack2(acc[q], lo, hi);
        h[2 * q]     = fmaxf(lo, 0.f);
        h[2 * q + 1] = fmaxf(hi, 0.f);
    }

    // ---- layer 4: 32 -> 1, sign (sigmoid(z)>=0.5 <=> z>=0) ----
    ull accA = 0ull, accB = 0ull;
    const ulonglong2* w4 = reinterpret_cast<const ulonglong2*>(sW4);
#pragma unroll
    for (int p = 0; p < 8; p++) {
        ulonglong2 w = w4[p];
        fma2(accA, pack2(h[4 * p],     h[4 * p + 1]), w.x);
        fma2(accB, pack2(h[4 * p + 2], h[4 * p + 3]), w.y);
    }
    float a0, a1, b0, b1;
    unpack2(accA, a0, a1);
    unpack2(accB, b0, b1);
    float z = (a0 + a1) + (b0 + b1);

    out[b * OUT_N + o] = (z >= 0.f) ? 1.f : -1.f;
}

// ---------------------------------------------------------------------------
extern "C" void kernel_launch(void* const* d_in, const int* in_sizes, int n_in,
                              void* d_out, int out_size)
{
    const float* inputs = (const float*)d_in[0];  // (B, IN)
    const float* mask   = (const float*)d_in[1];  // (OUT, IN)
    const float* W1     = (const float*)d_in[2];  // (OUT, IN, HID)
    const float* W2     = (const float*)d_in[3];  // (OUT, HID, HID)
    const float* W3     = (const float*)d_in[4];  // (OUT, HID, HID)
    const float* W4     = (const float*)d_in[5];  // (OUT, HID, 1)
    float* out = (float*)d_out;                   // (B, OUT)

    topk6_kernel<<<OUT_N, 32>>>(mask);
    dim3 tg(IN_N / 32, B_N / 32);
    transpose_kernel<<<tg, dim3(32, 8)>>>(inputs);
    mlp_kernel<<<OUT_N * 2, 128>>>(W1, W2, W3, W4, out);
}